// round 17
// baseline (speedup 1.0000x reference)
#include <cuda_runtime.h>
#include <cuda_fp16.h>
#include <cstdint>

#define D_MODEL  256
#define D_HIDDEN 1024
#define TM       64          // tokens per tile; 2 tiles per CTA

// ---- SMEM byte offsets ----
#define XF0_OFF    0                         // X A-frags tile0: 32KB
#define XF1_OFF    32768                     // X A-frags tile1: 32KB
#define HS_OFF     65536                     // HsF fragment-layout double buffer: 2 x 32KB
#define HS_BUF     32768
#define B1_OFF     (HS_OFF + 2 * HS_BUF)     // fp32 bias1: 4KB
#define B2_OFF     (B1_OFF + 4096)           // fp32 bias2: 1KB
#define SMEM_TOTAL (B2_OFF + 1024)           // 136192

// Pre-masked fp16 weights in m16n8k16 fragment-pair layout (see prep_weights). 512KB each.
__device__ __half g_w1h[D_HIDDEN * D_MODEL];
__device__ __half g_w2h[D_HIDDEN * D_MODEL];

// ======================= helpers =======================
__device__ __forceinline__ void mma_h(float c[4],
                                      uint32_t a0, uint32_t a1, uint32_t a2, uint32_t a3,
                                      uint32_t b0, uint32_t b1) {
    asm volatile(
        "mma.sync.aligned.m16n8k16.row.col.f32.f16.f16.f32 "
        "{%0,%1,%2,%3}, {%4,%5,%6,%7}, {%8,%9}, {%0,%1,%2,%3};\n"
        : "+f"(c[0]), "+f"(c[1]), "+f"(c[2]), "+f"(c[3])
        : "r"(a0), "r"(a1), "r"(a2), "r"(a3), "r"(b0), "r"(b1));
}
__device__ __forceinline__ uint32_t pack_h2(float x, float y) {
    __half2 h = __floats2half2_rn(x, y);
    return *reinterpret_cast<uint32_t*>(&h);
}

// ============ weight prep: mask + fp16 round + k16 fragment-pair pack ============
// (unchanged from passing R13-R16 kernels — layout verified)
__global__ void prep_weights(const float* __restrict__ w1,
                             const float* __restrict__ w2,
                             const int* __restrict__ mask) {
    int idx = blockIdx.x * blockDim.x + threadIdx.x;
    if (idx >= D_HIDDEN * D_MODEL) return;
    int h = idx >> 8;
    int d = idx & 255;
    float m = (mask[idx] != 0) ? 1.0f : 0.0f;

    // ---- W1: n = h (1024), k = d (256). jpg = h>>4 (64), kstep = d>>4 (16). ----
    {
        __half v = __float2half_rn(w1[idx] * m);
        int f4   = (((h >> 4) * 16) + (d >> 4)) * 32 + (h & 7) * 4 + ((d >> 1) & 3);
        int comp = ((h >> 3) & 1) * 2 + ((d & 15) >> 3);
        g_w1h[f4 * 8 + comp * 2 + (d & 1)] = v;
    }
    // ---- W2: n = d (256), k = h (1024). jpg = d>>4 (16), kstep = h>>4 (64). ----
    {
        __half v = __float2half_rn(w2[(size_t)d * D_HIDDEN + h] * m);
        int f4   = (((d >> 4) * 64) + (h >> 4)) * 32 + (d & 7) * 4 + ((h >> 1) & 3);
        int comp = ((d >> 3) & 1) * 2 + ((h & 15) >> 3);
        g_w2h[f4 * 8 + comp * 2 + (h & 1)] = v;
    }
}

// ======================= fused MLP: 2 tiles/CTA, cross-tile merged pipeline =======================
__global__ __launch_bounds__(256, 1)
void ffd_h16(const float* __restrict__ x,
             const float* __restrict__ b1,
             const float* __restrict__ b2,
             float* __restrict__ out,
             int n_tokens) {
    extern __shared__ char smem[];
    float* b1s = (float*)(smem + B1_OFF);
    float* b2s = (float*)(smem + B2_OFF);

    const int tid   = threadIdx.x;
    const int warp  = tid >> 5;    // 0..7
    const int lane  = tid & 31;
    const int g     = lane >> 2;
    const int q     = lane & 3;
    const int hcoff = warp >> 2;   // 0..1: 128-hidden block within 256-pass
    const int wq4   = warp & 3;    // 0..3: 32-col stripe within the 128 block
    const int W     = hcoff * 128 + wq4 * 32;   // warp's hidden-col base within a pass
    const int mt0   = blockIdx.x * (2 * TM);
    const int mt1   = mt0 + TM;

    // ---- X pack helper: one iteration i (0..15) into fragment layout ----
    auto pack_x = [&](int i, char* dstBase, int mtb) {
        int lin = tid + i * 256;          // 4096 float4 per tile
        int row = lin >> 6, c4 = lin & 63;
        int tok = mtb + row;
        float4 v = make_float4(0.f, 0.f, 0.f, 0.f);
        if (tok < n_tokens)
            v = *reinterpret_cast<const float4*>(x + (size_t)tok * D_MODEL + c4 * 4);
        int m     = row >> 4, gg = row & 7, rh = (row >> 3) & 1;
        int kstep = c4 >> 2;
        int reg   = (c4 >> 1) & 1;
        int comp  = reg * 2 + rh;
        int q0    = (c4 & 1) * 2;
        int f4    = (m * 16 + kstep) * 32 + gg * 4 + q0;
        *(uint32_t*)(dstBase + f4 * 16 + comp * 4)       = pack_h2(v.x, v.y);
        *(uint32_t*)(dstBase + (f4 + 1) * 16 + comp * 4) = pack_h2(v.z, v.w);
    };

    // ---- prologue: X(tile0) + biases ----
    #pragma unroll
    for (int i = 0; i < 16; i++) pack_x(i, smem + XF0_OFF, mt0);
    #pragma unroll
    for (int i = tid; i < D_HIDDEN; i += 256) b1s[i] = b1[i];
    b2s[tid] = b2[tid];
    __syncthreads();

    float yacc[4][2][2][4];
    #pragma unroll
    for (int m = 0; m < 4; m++)
        #pragma unroll
        for (int jp = 0; jp < 2; jp++)
            #pragma unroll
            for (int pr = 0; pr < 2; pr++)
                #pragma unroll
                for (int r = 0; r < 4; r++) yacc[m][jp][pr][r] = 0.f;

    float hacc[4][2][2][4];

    const uint4* W1f = (const uint4*)g_w1h;
    const uint4* W2f = (const uint4*)g_w2h;

    // ---- H epilogue: hacc -> HsF[buf] in fragment layout ----
    auto epilogueH = [&](int p, uint4* HsCur) {
        #pragma unroll
        for (int m = 0; m < 4; m++) {
            #pragma unroll
            for (int jp = 0; jp < 2; jp++) {
                int colLo = p * 256 + W + jp * 16 + 2 * q;
                float bb0  = b1s[colLo];
                float bb1  = b1s[colLo + 1];
                float bb0h = b1s[colLo + 8];
                float bb1h = b1s[colLo + 9];
                float* c0 = hacc[m][jp][0];
                float* c1 = hacc[m][jp][1];
                uint4 v;
                v.x = pack_h2(fmaxf(c0[0] + bb0,  0.f), fmaxf(c0[1] + bb1,  0.f));
                v.y = pack_h2(fmaxf(c0[2] + bb0,  0.f), fmaxf(c0[3] + bb1,  0.f));
                v.z = pack_h2(fmaxf(c1[0] + bb0h, 0.f), fmaxf(c1[1] + bb1h, 0.f));
                v.w = pack_h2(fmaxf(c1[2] + bb0h, 0.f), fmaxf(c1[3] + bb1h, 0.f));
                int ks = hcoff * 8 + wq4 * 2 + jp;
                HsCur[(m * 16 + ks) * 32 + lane] = v;
            }
        }
    };

    // ---- Y writeout: yacc + b2 -> out, then leave yacc stale (caller zeros) ----
    auto write_y = [&](int mtb) {
        #pragma unroll
        for (int m = 0; m < 4; m++) {
            int r0 = m * 16 + g;
            int tok0 = mtb + r0;
            int tok1 = tok0 + 8;
            #pragma unroll
            for (int jp = 0; jp < 2; jp++) {
                #pragma unroll
                for (int pr = 0; pr < 2; pr++) {
                    int d = warp * 32 + jp * 16 + pr * 8 + 2 * q;
                    float bb0 = b2s[d];
                    float bb1 = b2s[d + 1];
                    float* c = yacc[m][jp][pr];
                    if (tok0 < n_tokens) {
                        float2 v = make_float2(c[0] + bb0, c[1] + bb1);
                        *reinterpret_cast<float2*>(out + (size_t)tok0 * D_MODEL + d) = v;
                    }
                    if (tok1 < n_tokens) {
                        float2 v = make_float2(c[2] + bb0, c[3] + bb1);
                        *reinterpret_cast<float2*>(out + (size_t)tok1 * D_MODEL + d) = v;
                    }
                }
            }
        }
    };

    // ================= head: GEMM1(tile0, p=0) =================
    {
        #pragma unroll
        for (int m = 0; m < 4; m++)
            #pragma unroll
            for (int jp = 0; jp < 2; jp++)
                #pragma unroll
                for (int pr = 0; pr < 2; pr++)
                    #pragma unroll
                    for (int r = 0; r < 4; r++) hacc[m][jp][pr][r] = 0.f;

        const uint4* XsF4 = (const uint4*)(smem + XF0_OFF);
        const int jb = hcoff * 8 + wq4 * 2;
        const uint4* pW = W1f + (size_t)(jb * 16) * 32 + lane;
        uint4 B0c = __ldg(pW);
        uint4 B1c = __ldg(pW + 512);

        #pragma unroll
        for (int ks = 0; ks < 16; ks++) {
            uint4 B0n, B1n;
            if (ks < 15) {
                B0n = __ldg(pW + (ks + 1) * 32);
                B1n = __ldg(pW + 512 + (ks + 1) * 32);
            }
            #pragma unroll
            for (int m = 0; m < 4; m++) {
                uint4 A = XsF4[(m * 16 + ks) * 32 + lane];
                mma_h(hacc[m][0][0], A.x, A.y, A.z, A.w, B0c.x, B0c.y);
                mma_h(hacc[m][0][1], A.x, A.y, A.z, A.w, B0c.z, B0c.w);
                mma_h(hacc[m][1][0], A.x, A.y, A.z, A.w, B1c.x, B1c.y);
                mma_h(hacc[m][1][1], A.x, A.y, A.z, A.w, B1c.z, B1c.w);
            }
            B0c = B0n; B1c = B1n;
        }
        epilogueH(0, (uint4*)(smem + HS_OFF));
    }
    __syncthreads();

    // ================= merged global passes gp = 1..7 =================
    // GEMM1(tile gp>>2, pass gp&3)  +  GEMM2(tile (gp-1)>>2, pass (gp-1)&3)
    for (int gp = 1; gp < 8; gp++) {
        const int p1 = gp & 3;
        const int p2 = (gp - 1) & 3;
        const uint4* XsF4   = (const uint4*)(smem + ((gp < 4) ? XF0_OFF : XF1_OFF));
        const uint4* HsPrev = (const uint4*)(smem + HS_OFF + ((gp - 1) & 1) * HS_BUF);
        uint4*       HsCur  = (uint4*)(smem + HS_OFF + (gp & 1) * HS_BUF);

        #pragma unroll
        for (int m = 0; m < 4; m++)
            #pragma unroll
            for (int jp = 0; jp < 2; jp++)
                #pragma unroll
                for (int pr = 0; pr < 2; pr++)
                    #pragma unroll
                    for (int r = 0; r < 4; r++) hacc[m][jp][pr][r] = 0.f;

        const int jb = p1 * 16 + hcoff * 8 + wq4 * 2;
        const uint4* pW1 = W1f + (size_t)(jb * 16) * 32 + lane;
        const uint4* pW2 = W2f + (size_t)(warp * 2 * 64 + p2 * 16) * 32 + lane;

        uint4 B10 = __ldg(pW1);
        uint4 B11 = __ldg(pW1 + 512);
        uint4 B20 = __ldg(pW2);
        uint4 B21 = __ldg(pW2 + 2048);

        #pragma unroll
        for (int ks = 0; ks < 16; ks++) {
            uint4 B10n, B11n, B20n, B21n;
            if (ks < 15) {
                B10n = __ldg(pW1 + (ks + 1) * 32);
                B11n = __ldg(pW1 + 512 + (ks + 1) * 32);
                B20n = __ldg(pW2 + (ks + 1) * 32);
                B21n = __ldg(pW2 + 2048 + (ks + 1) * 32);
            }
            #pragma unroll
            for (int m = 0; m < 4; m++) {
                uint4 A  = XsF4[(m * 16 + ks) * 32 + lane];
                uint4 Ah = HsPrev[(m * 16 + ks) * 32 + lane];
                mma_h(hacc[m][0][0], A.x, A.y, A.z, A.w, B10.x, B10.y);
                mma_h(hacc[m][0][1], A.x, A.y, A.z, A.w, B10.z, B10.w);
                mma_h(hacc[m][1][0], A.x, A.y, A.z, A.w, B11.x, B11.y);
                mma_h(hacc[m][1][1], A.x, A.y, A.z, A.w, B11.z, B11.w);
                mma_h(yacc[m][0][0], Ah.x, Ah.y, Ah.z, Ah.w, B20.x, B20.y);
                mma_h(yacc[m][0][1], Ah.x, Ah.y, Ah.z, Ah.w, B20.z, B20.w);
                mma_h(yacc[m][1][0], Ah.x, Ah.y, Ah.z, Ah.w, B21.x, B21.y);
                mma_h(yacc[m][1][1], Ah.x, Ah.y, Ah.z, Ah.w, B21.z, B21.w);
            }
            B10 = B10n; B11 = B11n; B20 = B20n; B21 = B21n;
        }
        epilogueH(p1, HsCur);

        // stage X(tile1) in 3 chunks during gp = 1..3
        if (gp == 1)      { for (int i = 0;  i < 6;  i++) pack_x(i, smem + XF1_OFF, mt1); }
        else if (gp == 2) { for (int i = 6;  i < 11; i++) pack_x(i, smem + XF1_OFF, mt1); }
        else if (gp == 3) { for (int i = 11; i < 16; i++) pack_x(i, smem + XF1_OFF, mt1); }

        // tile0's Y complete after gp=4's GEMM2(tile0, p=3)
        if (gp == 4) {
            write_y(mt0);
            #pragma unroll
            for (int m = 0; m < 4; m++)
                #pragma unroll
                for (int jp = 0; jp < 2; jp++)
                    #pragma unroll
                    for (int pr = 0; pr < 2; pr++)
                        #pragma unroll
                        for (int r = 0; r < 4; r++) yacc[m][jp][pr][r] = 0.f;
        }
        __syncthreads();
    }

    // ================= tail: GEMM2(tile1, p=3) =================
    {
        const uint4* HsPrev = (const uint4*)(smem + HS_OFF + (7 & 1) * HS_BUF);
        const uint4* pW2 = W2f + (size_t)(warp * 2 * 64 + 3 * 16) * 32 + lane;
        uint4 B0c = __ldg(pW2);
        uint4 B1c = __ldg(pW2 + 2048);

        #pragma unroll
        for (int ks = 0; ks < 16; ks++) {
            uint4 B0n, B1n;
            if (ks < 15) {
                B0n = __ldg(pW2 + (ks + 1) * 32);
                B1n = __ldg(pW2 + 2048 + (ks + 1) * 32);
            }
            #pragma unroll
            for (int m = 0; m < 4; m++) {
                uint4 Ah = HsPrev[(m * 16 + ks) * 32 + lane];
                mma_h(yacc[m][0][0], Ah.x, Ah.y, Ah.z, Ah.w, B0c.x, B0c.y);
                mma_h(yacc[m][0][1], Ah.x, Ah.y, Ah.z, Ah.w, B0c.z, B0c.w);
                mma_h(yacc[m][1][0], Ah.x, Ah.y, Ah.z, Ah.w, B1c.x, B1c.y);
                mma_h(yacc[m][1][1], Ah.x, Ah.y, Ah.z, Ah.w, B1c.z, B1c.w);
            }
            B0c = B0n; B1c = B1n;
        }
    }
    write_y(mt1);
}

extern "C" void kernel_launch(void* const* d_in, const int* in_sizes, int n_in,
                              void* d_out, int out_size) {
    // inputs (metadata order): x, w1, b1, w2, b2, mask
    const float* x    = (const float*)d_in[0];
    const float* w1   = (const float*)d_in[1];
    const float* b1   = (const float*)d_in[2];
    const float* w2   = (const float*)d_in[3];
    const float* b2   = (const float*)d_in[4];
    const int*   mask = (const int*)d_in[5];
    float* out = (float*)d_out;

    const int n_tokens = in_sizes[0] / D_MODEL;

    prep_weights<<<(D_HIDDEN * D_MODEL + 255) / 256, 256>>>(w1, w2, mask);

    cudaFuncSetAttribute(ffd_h16, cudaFuncAttributeMaxDynamicSharedMemorySize, SMEM_TOTAL);
    const int grid = (n_tokens + 2 * TM - 1) / (2 * TM);
    ffd_h16<<<grid, 256, SMEM_TOTAL>>>(x, b1, b2, out, n_tokens);
}